// round 15
// baseline (speedup 1.0000x reference)
#include <cuda_runtime.h>
#include <cuda_bf16.h>
#include <cstdint>

// Problem constants
#define BB     4
#define NQ     1024
#define NK     2048
#define DIMT   1024
#define NH     16
#define DH     64
#define ROWS_Q (BB*NQ)                  // 4096
#define ROWS_K (BB*NK)                  // 8192
#define ROWS_TOT (ROWS_Q + 2*ROWS_K)    // 20480
#define KVPARTS 8

// GEMM1 tail-split constants: 1280 tiles total, 1184 full-K + 96 split-K(2)
#define G1_TILES     1280
#define G1_FULL      1184
#define G1_GRID      (G1_FULL + 2 * (G1_TILES - G1_FULL))   // 1376
#define SPLIT_ROW0   (148 * 128)                            // 18944

// prep grid layout: 2 LN rows per block
#define LN_BLKS      (ROWS_TOT / 2)                // 10240
#define W_BLKS       2048
#define Z_BLKS       (ROWS_TOT - SPLIT_ROW0)       // 1536

// Scratch (static device arrays: allocation-free per harness rules)
__device__ __nv_bfloat16 g_ah[(size_t)ROWS_TOT * DIMT];  // LN out, hi bf16
__device__ __nv_bfloat16 g_al[(size_t)ROWS_TOT * DIMT];  // LN out, lo bf16
__device__ float         g_f [(size_t)ROWS_TOT * DIMT];  // projected features (fp32)
__device__ float         g_Sp[KVPARTS*BB*NH*DH*DH];      // kv partial sums
__device__ __nv_bfloat16 g_oh[(size_t)ROWS_Q * DIMT];    // attn out, hi bf16
__device__ __nv_bfloat16 g_ol[(size_t)ROWS_Q * DIMT];    // attn out, lo bf16
__device__ __nv_bfloat16 g_wih[DIMT*DIMT], g_wil[DIMT*DIMT];  // W_in^T  hi/lo [N,K]
__device__ __nv_bfloat16 g_woh[DIMT*DIMT], g_wol[DIMT*DIMT];  // W_out^T hi/lo [N,K]

// ---------------------------------------------------------------------------
// Helpers
// ---------------------------------------------------------------------------
__device__ __forceinline__ uint32_t smem_u32(const void* p) {
    uint32_t a;
    asm("{ .reg .u64 t; cvta.to.shared.u64 t, %1; cvt.u32.u64 %0, t; }" : "=r"(a) : "l"(p));
    return a;
}
__device__ __forceinline__ void cp16(uint32_t saddr, const void* g) {
    asm volatile("cp.async.cg.shared.global [%0], [%1], 16;" :: "r"(saddr), "l"(g));
}
#define CP_COMMIT() asm volatile("cp.async.commit_group;" ::: "memory")
#define CP_WAIT(n)  asm volatile("cp.async.wait_group %0;" :: "n"(n) : "memory")

__device__ __forceinline__ void ldsm_x4(uint32_t* r, uint32_t addr) {
    asm volatile("ldmatrix.sync.aligned.m8n8.x4.shared.b16 {%0,%1,%2,%3}, [%4];"
                 : "=r"(r[0]), "=r"(r[1]), "=r"(r[2]), "=r"(r[3]) : "r"(addr));
}
__device__ __forceinline__ void mma16816(float* c, const uint32_t* a, const uint32_t* b) {
    asm volatile("mma.sync.aligned.m16n8k16.row.col.f32.bf16.bf16.f32 "
                 "{%0,%1,%2,%3}, {%4,%5,%6,%7}, {%8,%9}, {%0,%1,%2,%3};"
                 : "+f"(c[0]), "+f"(c[1]), "+f"(c[2]), "+f"(c[3])
                 : "r"(a[0]), "r"(a[1]), "r"(a[2]), "r"(a[3]), "r"(b[0]), "r"(b[1]));
}
__device__ __forceinline__ void split2(float x, __nv_bfloat16& h, __nv_bfloat16& l) {
    h = __float2bfloat16_rn(x);
    l = __float2bfloat16_rn(x - __bfloat162float(h));
}
__device__ __forceinline__ uint32_t packbf2(float a, float b) {
    return (uint32_t)__bfloat16_as_ushort(__float2bfloat16_rn(a)) |
           ((uint32_t)__bfloat16_as_ushort(__float2bfloat16_rn(b)) << 16);
}
// XOR chunk swizzle for 64B rows of 4x16B chunks: 16B-aligned, ldmatrix
// 8-row phases hit all 8 banks.
__device__ __forceinline__ uint32_t sw_off(uint32_t row, uint32_t chunk) {
    return row * 64u + (chunk ^ ((row >> 1) & 3u)) * 16u;
}
__device__ __forceinline__ const float* ln_src(
    int row, const float* q, const float* k, const float* v) {
    if (row < ROWS_Q)               return q + (size_t)row * DIMT;
    else if (row < ROWS_Q + ROWS_K) return k + (size_t)(row - ROWS_Q) * DIMT;
    else                            return v + (size_t)(row - ROWS_Q - ROWS_K) * DIMT;
}

// ---------------------------------------------------------------------------
// Kernel 1 (merged): LN (2 rows/block) | weight split | zero split region
// ---------------------------------------------------------------------------
__global__ void __launch_bounds__(256) prep_kernel(
    const float* __restrict__ q, const float* __restrict__ k,
    const float* __restrict__ v, const float* __restrict__ gamma,
    const float* __restrict__ beta,
    const float* __restrict__ W_in, const float* __restrict__ W_out)
{
    const int blk = blockIdx.x;
    const int t = threadIdx.x;

    if (blk >= LN_BLKS + W_BLKS) {
        int zrow = SPLIT_ROW0 + (blk - LN_BLKS - W_BLKS);
        reinterpret_cast<float4*>(g_f + (size_t)zrow * DIMT)[t] =
            make_float4(0.f, 0.f, 0.f, 0.f);
        return;
    }
    if (blk >= LN_BLKS) {
        __shared__ float ts[32][33];
        int wblk = blk - LN_BLKS;
        const float* W = (wblk < 1024) ? W_in : W_out;
        __nv_bfloat16* Th = (wblk < 1024) ? g_wih : g_woh;
        __nv_bfloat16* Tl = (wblk < 1024) ? g_wil : g_wol;
        wblk &= 1023;
        int n0 = (wblk & 31) * 32, k0 = (wblk >> 5) * 32;
        int tx = t & 31, ty = t >> 5;                    // 32 x 8
        #pragma unroll
        for (int j = 0; j < 4; j++)
            ts[ty + j * 8][tx] = W[(size_t)(k0 + ty + j * 8) * DIMT + n0 + tx];
        __syncthreads();
        #pragma unroll
        for (int j = 0; j < 4; j++) {
            int n = n0 + ty + j * 8, kk = k0 + tx;
            float x = ts[tx][ty + j * 8];
            __nv_bfloat16 h, l;
            split2(x, h, l);
            Th[(size_t)n * DIMT + kk] = h;
            Tl[(size_t)n * DIMT + kk] = l;
        }
        return;
    }

    const int row = blk * 2 + (t >> 7);
    const int u = t & 127;
    const float* src = ln_src(row, q, k, v);
    float4 x0 = reinterpret_cast<const float4*>(src)[2 * u];
    float4 x1 = reinterpret_cast<const float4*>(src)[2 * u + 1];

    float s  = (x0.x + x0.y + x0.z + x0.w) + (x1.x + x1.y + x1.z + x1.w);
    float ss = (x0.x*x0.x + x0.y*x0.y + x0.z*x0.z + x0.w*x0.w)
             + (x1.x*x1.x + x1.y*x1.y + x1.z*x1.z + x1.w*x1.w);
    #pragma unroll
    for (int o = 16; o > 0; o >>= 1) {
        s  += __shfl_xor_sync(0xffffffffu, s,  o);
        ss += __shfl_xor_sync(0xffffffffu, ss, o);
    }
    __shared__ float ws[2][4], wss[2][4];
    const int r = t >> 7, w_in = (t >> 5) & 3;
    if ((t & 31) == 0) { ws[r][w_in] = s; wss[r][w_in] = ss; }
    __syncthreads();
    float tot   = ws[r][0] + ws[r][1] + ws[r][2] + ws[r][3];
    float totss = wss[r][0] + wss[r][1] + wss[r][2] + wss[r][3];
    float mu  = tot * (1.0f / DIMT);
    float var = totss * (1.0f / DIMT) - mu * mu;       // biased, matches ref
    float rs  = rsqrtf(var + 1e-5f);

    float4 g0 = reinterpret_cast<const float4*>(gamma)[2 * u];
    float4 g1 = reinterpret_cast<const float4*>(gamma)[2 * u + 1];
    float4 b0 = reinterpret_cast<const float4*>(beta)[2 * u];
    float4 b1 = reinterpret_cast<const float4*>(beta)[2 * u + 1];

    float y[8];
    y[0] = (x0.x - mu) * rs * g0.x + b0.x;
    y[1] = (x0.y - mu) * rs * g0.y + b0.y;
    y[2] = (x0.z - mu) * rs * g0.z + b0.z;
    y[3] = (x0.w - mu) * rs * g0.w + b0.w;
    y[4] = (x1.x - mu) * rs * g1.x + b1.x;
    y[5] = (x1.y - mu) * rs * g1.y + b1.y;
    y[6] = (x1.z - mu) * rs * g1.z + b1.z;
    y[7] = (x1.w - mu) * rs * g1.w + b1.w;

    float hf[8], lf[8];
    #pragma unroll
    for (int i = 0; i < 8; i++) {
        __nv_bfloat16 h, l;
        split2(y[i], h, l);
        hf[i] = __bfloat162float(h);
        lf[i] = __bfloat162float(l);
    }
    uint4 uh = make_uint4(packbf2(hf[0], hf[1]), packbf2(hf[2], hf[3]),
                          packbf2(hf[4], hf[5]), packbf2(hf[6], hf[7]));
    uint4 ul = make_uint4(packbf2(lf[0], lf[1]), packbf2(lf[2], lf[3]),
                          packbf2(lf[4], lf[5]), packbf2(lf[6], lf[7]));
    reinterpret_cast<uint4*>(g_ah + (size_t)row * DIMT)[u] = uh;
    reinterpret_cast<uint4*>(g_al + (size_t)row * DIMT)[u] = ul;
}

// ---------------------------------------------------------------------------
// Kernel 2: mma.sync bf16x3 GEMM — proven 128x128 tile, 256 thr, 2 CTA/SM,
// flat grid with split-K tail wave (R13 shape; 256x128@1CTA regressed in R14).
// ---------------------------------------------------------------------------
#define BKG     32
#define ROWB    64                     // 64 B per row (32 bf16, unpadded)
#define TILE_B  (128 * ROWB)           // 8192 B per tensor tile
#define STAGE_B (4 * TILE_B)           // 32768 B per stage
#define GSMEM   (3 * STAGE_B)          // 98304 B total

__global__ void __launch_bounds__(256, 2) gemm_mma_bf16x3(
    const __nv_bfloat16* __restrict__ Ah, const __nv_bfloat16* __restrict__ Al,
    const __nv_bfloat16* __restrict__ Bh, const __nv_bfloat16* __restrict__ Bl,
    float* __restrict__ C, int M, int N, int K, const float* __restrict__ bias,
    int n_full)
{
    extern __shared__ char sm[];
    const uint32_t sbase = smem_u32(sm);
    const int tid = threadIdx.x;
    const int lane = tid & 31;
    const int wid = tid >> 5;
    const int warp_m = wid >> 2;        // 0..1
    const int warp_n = wid & 3;         // 0..3

    const int bid = blockIdx.x;
    int tile, k_begin, k_slabs;
    bool is_split;
    if (bid < n_full) {
        tile = bid; k_begin = 0; k_slabs = K / BKG; is_split = false;
    } else {
        int j = bid - n_full;
        tile = n_full + (j >> 1);
        k_begin = (j & 1) * (K / 2);
        k_slabs = K / (2 * BKG);
        is_split = true;
    }
    const int brow = tile >> 3, bcol = tile & 7;

    const __nv_bfloat16* tp[4] = {
        Ah + (size_t)brow * 128 * K + k_begin,
        Al + (size_t)brow * 128 * K + k_begin,
        Bh + (size_t)bcol * 128 * K + k_begin,
        Bl + (size_t)bcol * 128 * K + k_begin };

    int l_tens[8], l_row[8], l_ch[8];
    #pragma unroll
    for (int l = 0; l < 8; l++) {
        int id = l * 256 + tid;
        l_tens[l] = id >> 9;
        int u = id & 511;
        l_row[l] = u >> 2;
        l_ch[l] = u & 3;
    }

    float acc[4][4][4];
    #pragma unroll
    for (int i = 0; i < 4; i++)
        #pragma unroll
        for (int j = 0; j < 4; j++)
            #pragma unroll
            for (int c = 0; c < 4; c++) acc[i][j][c] = 0.f;

    #pragma unroll
    for (int pr = 0; pr < 2; pr++) {
        #pragma unroll
        for (int l = 0; l < 8; l++) {
            uint32_t sa = sbase + pr * STAGE_B + l_tens[l] * TILE_B
                        + sw_off((uint32_t)l_row[l], (uint32_t)l_ch[l]);
            cp16(sa, tp[l_tens[l]] + (size_t)l_row[l] * K + pr * BKG + l_ch[l] * 8);
        }
        CP_COMMIT();
    }

    const int b_rowlane = ((lane >> 4) & 1) * 8 + (lane & 7);
    const uint32_t b_kbit = (uint32_t)((lane >> 3) & 1);
    const uint32_t a_kbit = (uint32_t)(lane >> 4);
    const int bn = warp_n * 32;

    for (int ks = 0; ks < k_slabs; ks++) {
        if (ks + 2 < k_slabs) CP_WAIT(1); else CP_WAIT(0);
        __syncthreads();

        if (ks + 2 < k_slabs) {
            const int st = (ks + 2) % 3;
            const int k0 = (ks + 2) * BKG;
            #pragma unroll
            for (int l = 0; l < 8; l++) {
                uint32_t sa = sbase + st * STAGE_B + l_tens[l] * TILE_B
                            + sw_off((uint32_t)l_row[l], (uint32_t)l_ch[l]);
                cp16(sa, tp[l_tens[l]] + (size_t)l_row[l] * K + k0 + l_ch[l] * 8);
            }
            CP_COMMIT();
        }

        const uint32_t stb = sbase + (ks % 3) * STAGE_B;
        #pragma unroll
        for (int kk = 0; kk < 2; kk++) {
            const uint32_t bchunk = (uint32_t)(kk * 2) + b_kbit;
            const uint32_t achunk = (uint32_t)(kk * 2) + a_kbit;
            uint32_t bh[4][2], bl[4][2];
            #pragma unroll
            for (int p = 0; p < 2; p++) {
                uint32_t brr = (uint32_t)(bn + p * 16 + b_rowlane);
                uint32_t boff = sw_off(brr, bchunk);
                uint32_t r4[4];
                ldsm_x4(r4, stb + 2 * TILE_B + boff);
                bh[2*p][0] = r4[0]; bh[2*p][1] = r4[1];
                bh[2*p+1][0] = r4[2]; bh[2*p+1][1] = r4[3];
                ldsm_x4(r4, stb + 3 * TILE_B + boff);
                bl[2*p][0] = r4[0]; bl[2*p][1] = r4[1];
                bl[2*p+1][0] = r4[2]; bl[2*p+1][1] = r4[3];
            }
            #pragma unroll
            for (int mt = 0; mt < 4; mt++) {
                uint32_t ah4[4], al4[4];
                uint32_t arr = (uint32_t)(warp_m * 64 + mt * 16 + (lane & 15));
                uint32_t aoff = sw_off(arr, achunk);
                ldsm_x4(ah4, stb + aoff);
                ldsm_x4(al4, stb + TILE_B + aoff);
                #pragma unroll
                for (int nt = 0; nt < 4; nt++) mma16816(acc[mt][nt], ah4, bh[nt]);
                #pragma unroll
                for (int nt = 0; nt < 4; nt++) mma16816(acc[mt][nt], ah4, bl[nt]);
                #pragma unroll
                for (int nt = 0; nt < 4; nt++) mma16816(acc[mt][nt], al4, bh[nt]);
            }
        }
    }

    #pragma unroll
    for (int mt = 0; mt < 4; mt++) {
        const int row0 = brow * 128 + warp_m * 64 + mt * 16 + (lane >> 2);
        #pragma unroll
        for (int nt = 0; nt < 4; nt++) {
            const int col = bcol * 128 + warp_n * 32 + nt * 8 + (lane & 3) * 2;
            if (is_split) {
                atomicAdd(C + (size_t)row0 * N + col,           acc[mt][nt][0]);
                atomicAdd(C + (size_t)row0 * N + col + 1,       acc[mt][nt][1]);
                atomicAdd(C + (size_t)(row0 + 8) * N + col,     acc[mt][nt][2]);
                atomicAdd(C + (size_t)(row0 + 8) * N + col + 1, acc[mt][nt][3]);
            } else {
                float b0 = 0.f, b1 = 0.f;
                if (bias) { b0 = __ldg(&bias[col]); b1 = __ldg(&bias[col + 1]); }
                *reinterpret_cast<float2*>(C + (size_t)row0 * N + col) =
                    make_float2(acc[mt][nt][0] + b0, acc[mt][nt][1] + b1);
                *reinterpret_cast<float2*>(C + (size_t)(row0 + 8) * N + col) =
                    make_float2(acc[mt][nt][2] + b0, acc[mt][nt][3] + b1);
            }
        }
    }
}

// ---------------------------------------------------------------------------
// Kernel 3: kv partials. grid = (64, KVPARTS) -> 512 CTAs (full-chip).
// ---------------------------------------------------------------------------
__global__ void __launch_bounds__(256) kv_part_kernel()
{
    const int bh = blockIdx.x;
    const int part = blockIdx.y;
    const int b = bh >> 4, h = bh & 15;
    __shared__ float sk[32][64];
    __shared__ float sv[32][64];
    __shared__ float rkn[32];
    const int t = threadIdx.x;
    const int j1_0 = (t >> 4) << 2;
    const int j2_0 = (t & 15) << 2;
    const int mbase = part * (NK / KVPARTS);
    const float* fk = g_f + (size_t)(ROWS_Q + b * NK + mbase) * DIMT + h * DH;
    const float* fv = g_f + (size_t)(ROWS_Q + ROWS_K + b * NK + mbase) * DIMT + h * DH;

    float acc[4][4];
    #pragma unroll
    for (int i = 0; i < 4; i++)
        #pragma unroll
        for (int j = 0; j < 4; j++) acc[i][j] = 0.f;

    for (int m0 = 0; m0 < NK / KVPARTS; m0 += 32) {
        #pragma unroll
        for (int l = 0; l < 2; l++) {
            int idx = t + l * 256;
            int r = idx >> 4, c = (idx & 15) << 2;
            float4 kv4 = *reinterpret_cast<const float4*>(&fk[(size_t)(m0 + r) * DIMT + c]);
            float4 vv4 = *reinterpret_cast<const float4*>(&fv[(size_t)(m0 + r) * DIMT + c]);
            *reinterpret_cast<float4*>(&sk[r][c]) = kv4;
            *reinterpret_cast<float4*>(&sv[r][c]) = vv4;
            float s = kv4.x*kv4.x + kv4.y*kv4.y + kv4.z*kv4.z + kv4.w*kv4.w;
            #pragma unroll
            for (int o = 8; o > 0; o >>= 1) s += __shfl_xor_sync(0xffffffffu, s, o);
            if ((t & 15) == 0) rkn[r] = rsqrtf(s);
        }
        __syncthreads();
        #pragma unroll 8
        for (int m = 0; m < 32; m++) {
            float rk = rkn[m];
            float4 a  = *reinterpret_cast<float4*>(&sk[m][j1_0]);
            float4 bq = *reinterpret_cast<float4*>(&sv[m][j2_0]);
            float a0 = a.x * rk, a1 = a.y * rk, a2 = a.z * rk, a3 = a.w * rk;
            acc[0][0] = fmaf(a0, bq.x, acc[0][0]); acc[0][1] = fmaf(a0, bq.y, acc[0][1]);
            acc[0][2] = fmaf(a0, bq.z, acc[0][2]); acc[0][3] = fmaf(a0, bq.w, acc[0][3]);
            acc[1][0] = fmaf(a1, bq.x, acc[1][0]); acc[1][1] = fmaf(a1, bq.y, acc[1][1]);
            acc[1][2] = fmaf(a1, bq.z, acc[1][2]); acc[1][3] = fmaf(a1, bq.w, acc[1][3]);
            acc[2][0] = fmaf(a2, bq.x, acc[2][0]); acc[2][1] = fmaf(a2, bq.y, acc[2][1]);
            acc[2][2] = fmaf(a2, bq.z, acc[2][2]); acc[2][3] = fmaf(a2, bq.w, acc[2][3]);
            acc[3][0] = fmaf(a3, bq.x, acc[3][0]); acc[3][1] = fmaf(a3, bq.y, acc[3][1]);
            acc[3][2] = fmaf(a3, bq.z, acc[3][2]); acc[3][3] = fmaf(a3, bq.w, acc[3][3]);
        }
        __syncthreads();
    }
    float* Sp = g_Sp + ((size_t)part * (BB * NH) + bh) * (DH * DH);
    #pragma unroll
    for (int i = 0; i < 4; i++)
        *reinterpret_cast<float4*>(&Sp[(j1_0 + i) * DH + j2_0]) =
            make_float4(acc[i][0], acc[i][1], acc[i][2], acc[i][3]);
}

// ---------------------------------------------------------------------------
// Kernel 4: out_attn = (f_q/|f_q|) @ S[b,h]  -> bf16 hi/lo split.
// 128 q-rows per CTA; S reduced in-kernel from the 8 partials (fixed order).
// ---------------------------------------------------------------------------
#define QSMEM (64*64*4 + 128*68*4)     // 51200 B

__global__ void __launch_bounds__(256) qs_kernel()
{
    extern __shared__ float qsm[];
    float (*sS)[64] = reinterpret_cast<float(*)[64]>(qsm);
    float (*sq)[68] = reinterpret_cast<float(*)[68]>(qsm + 64 * 64);
    const int bh = blockIdx.y;
    const int nt = blockIdx.x;            // 8 tiles of 128 rows
    const int b = bh >> 4, h = bh & 15;
    const int t = threadIdx.x;

    // reduce 8 partials into sS (each thread owns 4 float4 slots)
    {
        float4 racc[4];
        const float4* P0 = reinterpret_cast<const float4*>(
            g_Sp + ((size_t)0 * (BB * NH) + bh) * (DH * DH));
        #pragma unroll
        for (int l = 0; l < 4; l++) racc[l] = P0[t + l * 256];
        #pragma unroll
        for (int p = 1; p < KVPARTS; p++) {
            const float4* Pp = reinterpret_cast<const float4*>(
                g_Sp + ((size_t)p * (BB * NH) + bh) * (DH * DH));
            #pragma unroll
            for (int l = 0; l < 4; l++) {
                float4 v = Pp[t + l * 256];
                racc[l].x += v.x; racc[l].y += v.y;
                racc[l].z += v.z; racc[l].w += v.w;
            }
        }
        #pragma unroll
        for (int l = 0; l < 4; l++)
            reinterpret_cast<float4*>(sS)[t + l * 256] = racc[l];
    }

    const float* fq = g_f + (size_t)(b * NQ + nt * 128) * DIMT + h * DH;
    #pragma unroll
    for (int l = 0; l < 8; l++) {
        int idx = t + l * 256;                 // 2048 float4s (128 rows x 16)
        int r = idx >> 4, c = (idx & 15) << 2;
        float4 x = *reinterpret_cast<const float4*>(&fq[(size_t)r * DIMT + c]);
        float s = x.x*x.x + x.y*x.y + x.z*x.z + x.w*x.w;
        #pragma unroll
        for (int o = 8; o > 0; o >>= 1) s += __shfl_xor_sync(0xffffffffu, s, o);
        float rq = rsqrtf(s);
        *reinterpret_cast<float4*>(&sq[r][c]) =
            make_float4(x.x * rq, x.y * rq, x.z * rq, x.w * rq);
    }
    __syncthreads();

    float acc[8][4];
    #pragma unroll
    for (int i = 0; i < 8; i++)
        #pragma unroll
        for (int j = 0; j < 4; j++) acc[i][j] = 0.f;
    const int r0 = (t >> 4) << 3, c0 = (t & 15) << 2;
    #pragma unroll 4
    for (int j1 = 0; j1 < 64; j1++) {
        float4 bq = *reinterpret_cast<float4*>(&sS[j1][c0]);
        #pragma unroll
        for (int i = 0; i < 8; i++) {
            float a = sq[r0 + i][j1];
            acc[i][0] = fmaf(a, bq.x, acc[i][0]);
            acc[i][1] = fmaf(a, bq.y, acc[i][1]);
            acc[i][2] = fmaf(a, bq.z, acc[i][2]);
            acc[i][3] = fmaf(a, bq.w, acc[i][3]);
        }
    }
    const size_t obase = (size_t)(b * NQ + nt * 128 + r0) * DIMT + h * DH + c0;
    #pragma unroll
    for (int i = 0; i < 8; i++) {
        __nv_bfloat16 h0, h1, h2, h3, l0, l1, l2, l3;
        split2(acc[i][0], h0, l0); split2(acc[i][1], h1, l1);
        split2(acc[i][2], h2, l2); split2(acc[i][3], h3, l3);
        ushort4 uh = make_ushort4(__bfloat16_as_ushort(h0), __bfloat16_as_ushort(h1),
                                  __bfloat16_as_ushort(h2), __bfloat16_as_ushort(h3));
        ushort4 ul = make_ushort4(__bfloat16_as_ushort(l0), __bfloat16_as_ushort(l1),
                                  __bfloat16_as_ushort(l2), __bfloat16_as_ushort(l3));
        *reinterpret_cast<ushort4*>(g_oh + obase + (size_t)i * DIMT) = uh;
        *reinterpret_cast<ushort4*>(g_ol + obase + (size_t)i * DIMT) = ul;
    }
}

// ---------------------------------------------------------------------------
extern "C" void kernel_launch(void* const* d_in, const int* in_sizes, int n_in,
                              void* d_out, int out_size)
{
    const float* q     = (const float*)d_in[0];
    const float* k     = (const float*)d_in[1];
    const float* v     = (const float*)d_in[2];
    const float* gamma = (const float*)d_in[3];
    const float* beta  = (const float*)d_in[4];
    const float* W_in  = (const float*)d_in[5];
    const float* W_out = (const float*)d_in[6];
    const float* b_out = (const float*)d_in[7];
    float* out = (float*)d_out;

    __nv_bfloat16 *p_ah, *p_al, *p_oh, *p_ol, *p_wih, *p_wil, *p_woh, *p_wol;
    float *p_f;
    cudaGetSymbolAddress((void**)&p_ah,  g_ah);
    cudaGetSymbolAddress((void**)&p_al,  g_al);
    cudaGetSymbolAddress((void**)&p_oh,  g_oh);
    cudaGetSymbolAddress((void**)&p_ol,  g_ol);
    cudaGetSymbolAddress((void**)&p_wih, g_wih);
    cudaGetSymbolAddress((void**)&p_wil, g_wil);
    cudaGetSymbolAddress((void**)&p_woh, g_woh);
    cudaGetSymbolAddress((void**)&p_wol, g_wol);
    cudaGetSymbolAddress((void**)&p_f,   g_f);

    cudaFuncSetAttribute(gemm_mma_bf16x3,
                         cudaFuncAttributeMaxDynamicSharedMemorySize, GSMEM);
    cudaFuncSetAttribute(qs_kernel,
                         cudaFuncAttributeMaxDynamicSharedMemorySize, QSMEM);

    // 1) LN + weight split + zero split-K region (one launch)
    prep_kernel<<<LN_BLKS + W_BLKS + Z_BLKS, 256>>>(q, k, v, gamma, beta, W_in, W_out);
    // 2) projection GEMM: 1184 full-K tiles + 96 tiles as 192 half-K CTAs
    gemm_mma_bf16x3<<<G1_GRID, 256, GSMEM>>>(
        p_ah, p_al, p_wih, p_wil, p_f, ROWS_TOT, DIMT, DIMT, nullptr, G1_FULL);
    // 3) per-(b,h) S partials
    kv_part_kernel<<<dim3(BB * NH, KVPARTS), 256>>>();
    // 4) attn = q_hat @ (reduced S) -> bf16 hi/lo (128 rows/CTA)
    qs_kernel<<<dim3(NQ / 128, BB * NH), 256, QSMEM>>>();
    // 5) output GEMM: 128x128 tiles, 256 CTAs, single wave
    gemm_mma_bf16x3<<<256, 256, GSMEM>>>(
        p_oh, p_ol, p_woh, p_wol, out, ROWS_Q, DIMT, DIMT, b_out, 256);
}

// round 16
// speedup vs baseline: 1.5480x; 1.5480x over previous
#include <cuda_runtime.h>
#include <cuda_bf16.h>
#include <cstdint>

// Problem constants
#define BB     4
#define NQ     1024
#define NK     2048
#define DIMT   1024
#define NH     16
#define DH     64
#define ROWS_Q (BB*NQ)                  // 4096
#define ROWS_K (BB*NK)                  // 8192
#define ROWS_TOT (ROWS_Q + 2*ROWS_K)    // 20480
#define KVPARTS 8

// GEMM1 tail-split constants: 1280 tiles total, 1184 full-K + 96 split-K(2)
#define G1_TILES     1280
#define G1_FULL      1184
#define G1_GRID      (G1_FULL + 2 * (G1_TILES - G1_FULL))   // 1376
#define SPLIT_ROW0   (148 * 128)                            // 18944

// prep grid layout: 2 LN rows per block
#define LN_BLKS      (ROWS_TOT / 2)                // 10240
#define W_BLKS       2048
#define Z_BLKS       (ROWS_TOT - SPLIT_ROW0)       // 1536

// Scratch (static device arrays: allocation-free per harness rules)
__device__ __nv_bfloat16 g_ah[(size_t)ROWS_TOT * DIMT];  // LN out, hi bf16
__device__ __nv_bfloat16 g_al[(size_t)ROWS_TOT * DIMT];  // LN out, lo bf16
__device__ float         g_f [(size_t)ROWS_TOT * DIMT];  // projected features (fp32)
__device__ float         g_Sp[KVPARTS*BB*NH*DH*DH];      // kv partial sums
__device__ __nv_bfloat16 g_oh[(size_t)ROWS_Q * DIMT];    // attn out, hi bf16
__device__ __nv_bfloat16 g_ol[(size_t)ROWS_Q * DIMT];    // attn out, lo bf16
__device__ __nv_bfloat16 g_wih[DIMT*DIMT], g_wil[DIMT*DIMT];  // W_in^T  hi/lo [N,K]
__device__ __nv_bfloat16 g_woh[DIMT*DIMT], g_wol[DIMT*DIMT];  // W_out^T hi/lo [N,K]

// ---------------------------------------------------------------------------
// Helpers
// ---------------------------------------------------------------------------
__device__ __forceinline__ uint32_t smem_u32(const void* p) {
    uint32_t a;
    asm("{ .reg .u64 t; cvta.to.shared.u64 t, %1; cvt.u32.u64 %0, t; }" : "=r"(a) : "l"(p));
    return a;
}
__device__ __forceinline__ void cp16(uint32_t saddr, const void* g) {
    asm volatile("cp.async.cg.shared.global [%0], [%1], 16;" :: "r"(saddr), "l"(g));
}
#define CP_COMMIT() asm volatile("cp.async.commit_group;" ::: "memory")
#define CP_WAIT(n)  asm volatile("cp.async.wait_group %0;" :: "n"(n) : "memory")

__device__ __forceinline__ void ldsm_x4(uint32_t* r, uint32_t addr) {
    asm volatile("ldmatrix.sync.aligned.m8n8.x4.shared.b16 {%0,%1,%2,%3}, [%4];"
                 : "=r"(r[0]), "=r"(r[1]), "=r"(r[2]), "=r"(r[3]) : "r"(addr));
}
__device__ __forceinline__ void mma16816(float* c, const uint32_t* a, const uint32_t* b) {
    asm volatile("mma.sync.aligned.m16n8k16.row.col.f32.bf16.bf16.f32 "
                 "{%0,%1,%2,%3}, {%4,%5,%6,%7}, {%8,%9}, {%0,%1,%2,%3};"
                 : "+f"(c[0]), "+f"(c[1]), "+f"(c[2]), "+f"(c[3])
                 : "r"(a[0]), "r"(a[1]), "r"(a[2]), "r"(a[3]), "r"(b[0]), "r"(b[1]));
}
__device__ __forceinline__ void split2(float x, __nv_bfloat16& h, __nv_bfloat16& l) {
    h = __float2bfloat16_rn(x);
    l = __float2bfloat16_rn(x - __bfloat162float(h));
}
__device__ __forceinline__ uint32_t packbf2(float a, float b) {
    return (uint32_t)__bfloat16_as_ushort(__float2bfloat16_rn(a)) |
           ((uint32_t)__bfloat16_as_ushort(__float2bfloat16_rn(b)) << 16);
}
// XOR chunk swizzle for 64B rows of 4x16B chunks: 16B-aligned, ldmatrix
// 8-row phases hit all 8 banks.
__device__ __forceinline__ uint32_t sw_off(uint32_t row, uint32_t chunk) {
    return row * 64u + (chunk ^ ((row >> 1) & 3u)) * 16u;
}
__device__ __forceinline__ const float* ln_src(
    int row, const float* q, const float* k, const float* v) {
    if (row < ROWS_Q)               return q + (size_t)row * DIMT;
    else if (row < ROWS_Q + ROWS_K) return k + (size_t)(row - ROWS_Q) * DIMT;
    else                            return v + (size_t)(row - ROWS_Q - ROWS_K) * DIMT;
}

// ---------------------------------------------------------------------------
// Kernel 1 (merged): LN (2 rows/block) | weight split | zero split region
// ---------------------------------------------------------------------------
__global__ void __launch_bounds__(256) prep_kernel(
    const float* __restrict__ q, const float* __restrict__ k,
    const float* __restrict__ v, const float* __restrict__ gamma,
    const float* __restrict__ beta,
    const float* __restrict__ W_in, const float* __restrict__ W_out)
{
    const int blk = blockIdx.x;
    const int t = threadIdx.x;

    if (blk >= LN_BLKS + W_BLKS) {
        int zrow = SPLIT_ROW0 + (blk - LN_BLKS - W_BLKS);
        reinterpret_cast<float4*>(g_f + (size_t)zrow * DIMT)[t] =
            make_float4(0.f, 0.f, 0.f, 0.f);
        return;
    }
    if (blk >= LN_BLKS) {
        __shared__ float ts[32][33];
        int wblk = blk - LN_BLKS;
        const float* W = (wblk < 1024) ? W_in : W_out;
        __nv_bfloat16* Th = (wblk < 1024) ? g_wih : g_woh;
        __nv_bfloat16* Tl = (wblk < 1024) ? g_wil : g_wol;
        wblk &= 1023;
        int n0 = (wblk & 31) * 32, k0 = (wblk >> 5) * 32;
        int tx = t & 31, ty = t >> 5;                    // 32 x 8
        #pragma unroll
        for (int j = 0; j < 4; j++)
            ts[ty + j * 8][tx] = W[(size_t)(k0 + ty + j * 8) * DIMT + n0 + tx];
        __syncthreads();
        #pragma unroll
        for (int j = 0; j < 4; j++) {
            int n = n0 + ty + j * 8, kk = k0 + tx;
            float x = ts[tx][ty + j * 8];
            __nv_bfloat16 h, l;
            split2(x, h, l);
            Th[(size_t)n * DIMT + kk] = h;
            Tl[(size_t)n * DIMT + kk] = l;
        }
        return;
    }

    const int row = blk * 2 + (t >> 7);
    const int u = t & 127;
    const float* src = ln_src(row, q, k, v);
    float4 x0 = reinterpret_cast<const float4*>(src)[2 * u];
    float4 x1 = reinterpret_cast<const float4*>(src)[2 * u + 1];

    float s  = (x0.x + x0.y + x0.z + x0.w) + (x1.x + x1.y + x1.z + x1.w);
    float ss = (x0.x*x0.x + x0.y*x0.y + x0.z*x0.z + x0.w*x0.w)
             + (x1.x*x1.x + x1.y*x1.y + x1.z*x1.z + x1.w*x1.w);
    #pragma unroll
    for (int o = 16; o > 0; o >>= 1) {
        s  += __shfl_xor_sync(0xffffffffu, s,  o);
        ss += __shfl_xor_sync(0xffffffffu, ss, o);
    }
    __shared__ float ws[2][4], wss[2][4];
    const int r = t >> 7, w_in = (t >> 5) & 3;
    if ((t & 31) == 0) { ws[r][w_in] = s; wss[r][w_in] = ss; }
    __syncthreads();
    float tot   = ws[r][0] + ws[r][1] + ws[r][2] + ws[r][3];
    float totss = wss[r][0] + wss[r][1] + wss[r][2] + wss[r][3];
    float mu  = tot * (1.0f / DIMT);
    float var = totss * (1.0f / DIMT) - mu * mu;       // biased, matches ref
    float rs  = rsqrtf(var + 1e-5f);

    float4 g0 = reinterpret_cast<const float4*>(gamma)[2 * u];
    float4 g1 = reinterpret_cast<const float4*>(gamma)[2 * u + 1];
    float4 b0 = reinterpret_cast<const float4*>(beta)[2 * u];
    float4 b1 = reinterpret_cast<const float4*>(beta)[2 * u + 1];

    float y[8];
    y[0] = (x0.x - mu) * rs * g0.x + b0.x;
    y[1] = (x0.y - mu) * rs * g0.y + b0.y;
    y[2] = (x0.z - mu) * rs * g0.z + b0.z;
    y[3] = (x0.w - mu) * rs * g0.w + b0.w;
    y[4] = (x1.x - mu) * rs * g1.x + b1.x;
    y[5] = (x1.y - mu) * rs * g1.y + b1.y;
    y[6] = (x1.z - mu) * rs * g1.z + b1.z;
    y[7] = (x1.w - mu) * rs * g1.w + b1.w;

    float hf[8], lf[8];
    #pragma unroll
    for (int i = 0; i < 8; i++) {
        __nv_bfloat16 h, l;
        split2(y[i], h, l);
        hf[i] = __bfloat162float(h);
        lf[i] = __bfloat162float(l);
    }
    uint4 uh = make_uint4(packbf2(hf[0], hf[1]), packbf2(hf[2], hf[3]),
                          packbf2(hf[4], hf[5]), packbf2(hf[6], hf[7]));
    uint4 ul = make_uint4(packbf2(lf[0], lf[1]), packbf2(lf[2], lf[3]),
                          packbf2(lf[4], lf[5]), packbf2(lf[6], lf[7]));
    reinterpret_cast<uint4*>(g_ah + (size_t)row * DIMT)[u] = uh;
    reinterpret_cast<uint4*>(g_al + (size_t)row * DIMT)[u] = ul;
}

// ---------------------------------------------------------------------------
// Kernel 2: mma.sync bf16x3 GEMM, flat grid with split-K tail wave.
// ---------------------------------------------------------------------------
#define BKG     32
#define ROWB    64                     // 64 B per row (32 bf16, unpadded)
#define TILE_B  (128 * ROWB)           // 8192 B per tensor tile
#define STAGE_B (4 * TILE_B)           // 32768 B per stage
#define GSMEM   (3 * STAGE_B)          // 98304 B total

__global__ void __launch_bounds__(256, 2) gemm_mma_bf16x3(
    const __nv_bfloat16* __restrict__ Ah, const __nv_bfloat16* __restrict__ Al,
    const __nv_bfloat16* __restrict__ Bh, const __nv_bfloat16* __restrict__ Bl,
    float* __restrict__ C, int M, int N, int K, const float* __restrict__ bias,
    int n_full)
{
    extern __shared__ char sm[];
    const uint32_t sbase = smem_u32(sm);
    const int tid = threadIdx.x;
    const int lane = tid & 31;
    const int wid = tid >> 5;
    const int warp_m = wid >> 2;        // 0..1
    const int warp_n = wid & 3;         // 0..3

    const int bid = blockIdx.x;
    int tile, k_begin, k_slabs;
    bool is_split;
    if (bid < n_full) {
        tile = bid; k_begin = 0; k_slabs = K / BKG; is_split = false;
    } else {
        int j = bid - n_full;
        tile = n_full + (j >> 1);
        k_begin = (j & 1) * (K / 2);
        k_slabs = K / (2 * BKG);
        is_split = true;
    }
    const int brow = tile >> 3, bcol = tile & 7;

    const __nv_bfloat16* tp[4] = {
        Ah + (size_t)brow * 128 * K + k_begin,
        Al + (size_t)brow * 128 * K + k_begin,
        Bh + (size_t)bcol * 128 * K + k_begin,
        Bl + (size_t)bcol * 128 * K + k_begin };

    int l_tens[8], l_row[8], l_ch[8];
    #pragma unroll
    for (int l = 0; l < 8; l++) {
        int id = l * 256 + tid;
        l_tens[l] = id >> 9;
        int u = id & 511;
        l_row[l] = u >> 2;
        l_ch[l] = u & 3;
    }

    float acc[4][4][4];
    #pragma unroll
    for (int i = 0; i < 4; i++)
        #pragma unroll
        for (int j = 0; j < 4; j++)
            #pragma unroll
            for (int c = 0; c < 4; c++) acc[i][j][c] = 0.f;

    #pragma unroll
    for (int pr = 0; pr < 2; pr++) {
        #pragma unroll
        for (int l = 0; l < 8; l++) {
            uint32_t sa = sbase + pr * STAGE_B + l_tens[l] * TILE_B
                        + sw_off((uint32_t)l_row[l], (uint32_t)l_ch[l]);
            cp16(sa, tp[l_tens[l]] + (size_t)l_row[l] * K + pr * BKG + l_ch[l] * 8);
        }
        CP_COMMIT();
    }

    const int b_rowlane = ((lane >> 4) & 1) * 8 + (lane & 7);
    const uint32_t b_kbit = (uint32_t)((lane >> 3) & 1);
    const uint32_t a_kbit = (uint32_t)(lane >> 4);
    const int bn = warp_n * 32;

    for (int ks = 0; ks < k_slabs; ks++) {
        if (ks + 2 < k_slabs) CP_WAIT(1); else CP_WAIT(0);
        __syncthreads();

        if (ks + 2 < k_slabs) {
            const int st = (ks + 2) % 3;
            const int k0 = (ks + 2) * BKG;
            #pragma unroll
            for (int l = 0; l < 8; l++) {
                uint32_t sa = sbase + st * STAGE_B + l_tens[l] * TILE_B
                            + sw_off((uint32_t)l_row[l], (uint32_t)l_ch[l]);
                cp16(sa, tp[l_tens[l]] + (size_t)l_row[l] * K + k0 + l_ch[l] * 8);
            }
            CP_COMMIT();
        }

        const uint32_t stb = sbase + (ks % 3) * STAGE_B;
        #pragma unroll
        for (int kk = 0; kk < 2; kk++) {
            const uint32_t bchunk = (uint32_t)(kk * 2) + b_kbit;
            const uint32_t achunk = (uint32_t)(kk * 2) + a_kbit;
            uint32_t bh[4][2], bl[4][2];
            #pragma unroll
            for (int p = 0; p < 2; p++) {
                uint32_t brr = (uint32_t)(bn + p * 16 + b_rowlane);
                uint32_t boff = sw_off(brr, bchunk);
                uint32_t r4[4];
                ldsm_x4(r4, stb + 2 * TILE_B + boff);
                bh[2*p][0] = r4[0]; bh[2*p][1] = r4[1];
                bh[2*p+1][0] = r4[2]; bh[2*p+1][1] = r4[3];
                ldsm_x4(r4, stb + 3 * TILE_B + boff);
                bl[2*p][0] = r4[0]; bl[2*p][1] = r4[1];
                bl[2*p+1][0] = r4[2]; bl[2*p+1][1] = r4[3];
            }
            #pragma unroll
            for (int mt = 0; mt < 4; mt++) {
                uint32_t ah4[4], al4[4];
                uint32_t arr = (uint32_t)(warp_m * 64 + mt * 16 + (lane & 15));
                uint32_t aoff = sw_off(arr, achunk);
                ldsm_x4(ah4, stb + aoff);
                ldsm_x4(al4, stb + TILE_B + aoff);
                #pragma unroll
                for (int nt = 0; nt < 4; nt++) mma16816(acc[mt][nt], ah4, bh[nt]);
                #pragma unroll
                for (int nt = 0; nt < 4; nt++) mma16816(acc[mt][nt], ah4, bl[nt]);
                #pragma unroll
                for (int nt = 0; nt < 4; nt++) mma16816(acc[mt][nt], al4, bh[nt]);
            }
        }
    }

    #pragma unroll
    for (int mt = 0; mt < 4; mt++) {
        const int row0 = brow * 128 + warp_m * 64 + mt * 16 + (lane >> 2);
        #pragma unroll
        for (int nt = 0; nt < 4; nt++) {
            const int col = bcol * 128 + warp_n * 32 + nt * 8 + (lane & 3) * 2;
            if (is_split) {
                atomicAdd(C + (size_t)row0 * N + col,           acc[mt][nt][0]);
                atomicAdd(C + (size_t)row0 * N + col + 1,       acc[mt][nt][1]);
                atomicAdd(C + (size_t)(row0 + 8) * N + col,     acc[mt][nt][2]);
                atomicAdd(C + (size_t)(row0 + 8) * N + col + 1, acc[mt][nt][3]);
            } else {
                float b0 = 0.f, b1 = 0.f;
                if (bias) { b0 = __ldg(&bias[col]); b1 = __ldg(&bias[col + 1]); }
                *reinterpret_cast<float2*>(C + (size_t)row0 * N + col) =
                    make_float2(acc[mt][nt][0] + b0, acc[mt][nt][1] + b1);
                *reinterpret_cast<float2*>(C + (size_t)(row0 + 8) * N + col) =
                    make_float2(acc[mt][nt][2] + b0, acc[mt][nt][3] + b1);
            }
        }
    }
}

// ---------------------------------------------------------------------------
// Kernel 3: kv partials. grid = (64, KVPARTS) -> 512 CTAs (full-chip).
// ---------------------------------------------------------------------------
__global__ void __launch_bounds__(256) kv_part_kernel()
{
    const int bh = blockIdx.x;
    const int part = blockIdx.y;
    const int b = bh >> 4, h = bh & 15;
    __shared__ float sk[32][64];
    __shared__ float sv[32][64];
    __shared__ float rkn[32];
    const int t = threadIdx.x;
    const int j1_0 = (t >> 4) << 2;
    const int j2_0 = (t & 15) << 2;
    const int mbase = part * (NK / KVPARTS);
    const float* fk = g_f + (size_t)(ROWS_Q + b * NK + mbase) * DIMT + h * DH;
    const float* fv = g_f + (size_t)(ROWS_Q + ROWS_K + b * NK + mbase) * DIMT + h * DH;

    float acc[4][4];
    #pragma unroll
    for (int i = 0; i < 4; i++)
        #pragma unroll
        for (int j = 0; j < 4; j++) acc[i][j] = 0.f;

    for (int m0 = 0; m0 < NK / KVPARTS; m0 += 32) {
        #pragma unroll
        for (int l = 0; l < 2; l++) {
            int idx = t + l * 256;
            int r = idx >> 4, c = (idx & 15) << 2;
            float4 kv4 = *reinterpret_cast<const float4*>(&fk[(size_t)(m0 + r) * DIMT + c]);
            float4 vv4 = *reinterpret_cast<const float4*>(&fv[(size_t)(m0 + r) * DIMT + c]);
            *reinterpret_cast<float4*>(&sk[r][c]) = kv4;
            *reinterpret_cast<float4*>(&sv[r][c]) = vv4;
            float s = kv4.x*kv4.x + kv4.y*kv4.y + kv4.z*kv4.z + kv4.w*kv4.w;
            #pragma unroll
            for (int o = 8; o > 0; o >>= 1) s += __shfl_xor_sync(0xffffffffu, s, o);
            if ((t & 15) == 0) rkn[r] = rsqrtf(s);
        }
        __syncthreads();
        #pragma unroll 8
        for (int m = 0; m < 32; m++) {
            float rk = rkn[m];
            float4 a  = *reinterpret_cast<float4*>(&sk[m][j1_0]);
            float4 bq = *reinterpret_cast<float4*>(&sv[m][j2_0]);
            float a0 = a.x * rk, a1 = a.y * rk, a2 = a.z * rk, a3 = a.w * rk;
            acc[0][0] = fmaf(a0, bq.x, acc[0][0]); acc[0][1] = fmaf(a0, bq.y, acc[0][1]);
            acc[0][2] = fmaf(a0, bq.z, acc[0][2]); acc[0][3] = fmaf(a0, bq.w, acc[0][3]);
            acc[1][0] = fmaf(a1, bq.x, acc[1][0]); acc[1][1] = fmaf(a1, bq.y, acc[1][1]);
            acc[1][2] = fmaf(a1, bq.z, acc[1][2]); acc[1][3] = fmaf(a1, bq.w, acc[1][3]);
            acc[2][0] = fmaf(a2, bq.x, acc[2][0]); acc[2][1] = fmaf(a2, bq.y, acc[2][1]);
            acc[2][2] = fmaf(a2, bq.z, acc[2][2]); acc[2][3] = fmaf(a2, bq.w, acc[2][3]);
            acc[3][0] = fmaf(a3, bq.x, acc[3][0]); acc[3][1] = fmaf(a3, bq.y, acc[3][1]);
            acc[3][2] = fmaf(a3, bq.z, acc[3][2]); acc[3][3] = fmaf(a3, bq.w, acc[3][3]);
        }
        __syncthreads();
    }
    float* Sp = g_Sp + ((size_t)part * (BB * NH) + bh) * (DH * DH);
    #pragma unroll
    for (int i = 0; i < 4; i++)
        *reinterpret_cast<float4*>(&Sp[(j1_0 + i) * DH + j2_0]) =
            make_float4(acc[i][0], acc[i][1], acc[i][2], acc[i][3]);
}

// ---------------------------------------------------------------------------
// Kernel 4: out_attn = (f_q/|f_q|) @ S[b,h]  -> bf16 hi/lo split.
// 64 q-rows per CTA (R13 shape); S reduced in-kernel from the 8 partials.
// ---------------------------------------------------------------------------
__global__ void __launch_bounds__(256) qs_kernel()
{
    const int bh = blockIdx.y;
    const int nt = blockIdx.x;
    const int b = bh >> 4, h = bh & 15;
    __shared__ float sS[64][64];
    __shared__ float sq[64][68];          // row-major, norm folded
    const int t = threadIdx.x;

    // reduce 8 partials into sS (each thread owns 4 float4 slots)
    {
        float4 racc[4];
        const float4* P0 = reinterpret_cast<const float4*>(
            g_Sp + ((size_t)0 * (BB * NH) + bh) * (DH * DH));
        #pragma unroll
        for (int l = 0; l < 4; l++) racc[l] = P0[t + l * 256];
        #pragma unroll
        for (int p = 1; p < KVPARTS; p++) {
            const float4* Pp = reinterpret_cast<const float4*>(
                g_Sp + ((size_t)p * (BB * NH) + bh) * (DH * DH));
            #pragma unroll
            for (int l = 0; l < 4; l++) {
                float4 v = Pp[t + l * 256];
                racc[l].x += v.x; racc[l].y += v.y;
                racc[l].z += v.z; racc[l].w += v.w;
            }
        }
        #pragma unroll
        for (int l = 0; l < 4; l++)
            reinterpret_cast<float4*>(sS)[t + l * 256] = racc[l];
    }

    const float* fq = g_f + (size_t)(b * NQ + nt * 64) * DIMT + h * DH;
    #pragma unroll
    for (int l = 0; l < 4; l++) {
        int idx = t + l * 256;
        int r = idx >> 4, c = (idx & 15) << 2;
        float4 x = *reinterpret_cast<const float4*>(&fq[(size_t)r * DIMT + c]);
        float s = x.x*x.x + x.y*x.y + x.z*x.z + x.w*x.w;
        #pragma unroll
        for (int o = 8; o > 0; o >>= 1) s += __shfl_xor_sync(0xffffffffu, s, o);
        float rq = rsqrtf(s);
        *reinterpret_cast<float4*>(&sq[r][c]) =
            make_float4(x.x * rq, x.y * rq, x.z * rq, x.w * rq);
    }
    __syncthreads();

    float acc[4][4];
    #pragma unroll
    for (int i = 0; i < 4; i++)
        #pragma unroll
        for (int j = 0; j < 4; j++) acc[i][j] = 0.f;
    const int r0 = (t >> 4) << 2, c0 = (t & 15) << 2;
    #pragma unroll 8
    for (int j1 = 0; j1 < 64; j1++) {
        float a0 = sq[r0 + 0][j1];
        float a1 = sq[r0 + 1][j1];
        float a2 = sq[r0 + 2][j1];
        float a3 = sq[r0 + 3][j1];
        float4 bq = *reinterpret_cast<float4*>(&sS[j1][c0]);
        acc[0][0] = fmaf(a0, bq.x, acc[0][0]); acc[0][1] = fmaf(a0, bq.y, acc[0][1]);
        acc[0][2] = fmaf(a0, bq.z, acc[0][2]); acc[0][3] = fmaf(a0, bq.w, acc[0][3]);
        acc[1][0] = fmaf(a1, bq.x, acc[1][0]); acc[1][1] = fmaf(a1, bq.y, acc[1][1]);
        acc[1][2] = fmaf(a1, bq.z, acc[1][2]); acc[1][3] = fmaf(a1, bq.w, acc[1][3]);
        acc[2][0] = fmaf(a2, bq.x, acc[2][0]); acc[2][1] = fmaf(a2, bq.y, acc[2][1]);
        acc[2][2] = fmaf(a2, bq.z, acc[2][2]); acc[2][3] = fmaf(a2, bq.w, acc[2][3]);
        acc[3][0] = fmaf(a3, bq.x, acc[3][0]); acc[3][1] = fmaf(a3, bq.y, acc[3][1]);
        acc[3][2] = fmaf(a3, bq.z, acc[3][2]); acc[3][3] = fmaf(a3, bq.w, acc[3][3]);
    }
    const size_t obase = (size_t)(b * NQ + nt * 64 + r0) * DIMT + h * DH + c0;
    #pragma unroll
    for (int i = 0; i < 4; i++) {
        __nv_bfloat16 h0, h1, h2, h3, l0, l1, l2, l3;
        split2(acc[i][0], h0, l0); split2(acc[i][1], h1, l1);
        split2(acc[i][2], h2, l2); split2(acc[i][3], h3, l3);
        ushort4 uh = make_ushort4(__bfloat16_as_ushort(h0), __bfloat16_as_ushort(h1),
                                  __bfloat16_as_ushort(h2), __bfloat16_as_ushort(h3));
        ushort4 ul = make_ushort4(__bfloat16_as_ushort(l0), __bfloat16_as_ushort(l1),
                                  __bfloat16_as_ushort(l2), __bfloat16_as_ushort(l3));
        *reinterpret_cast<ushort4*>(g_oh + obase + (size_t)i * DIMT) = uh;
        *reinterpret_cast<ushort4*>(g_ol + obase + (size_t)i * DIMT) = ul;
    }
}

// ---------------------------------------------------------------------------
extern "C" void kernel_launch(void* const* d_in, const int* in_sizes, int n_in,
                              void* d_out, int out_size)
{
    const float* q     = (const float*)d_in[0];
    const float* k     = (const float*)d_in[1];
    const float* v     = (const float*)d_in[2];
    const float* gamma = (const float*)d_in[3];
    const float* beta  = (const float*)d_in[4];
    const float* W_in  = (const float*)d_in[5];
    const float* W_out = (const float*)d_in[6];
    const float* b_out = (const float*)d_in[7];
    float* out = (float*)d_out;

    __nv_bfloat16 *p_ah, *p_al, *p_oh, *p_ol, *p_wih, *p_wil, *p_woh, *p_wol;
    float *p_f;
    cudaGetSymbolAddress((void**)&p_ah,  g_ah);
    cudaGetSymbolAddress((void**)&p_al,  g_al);
    cudaGetSymbolAddress((void**)&p_oh,  g_oh);
    cudaGetSymbolAddress((void**)&p_ol,  g_ol);
    cudaGetSymbolAddress((void**)&p_wih, g_wih);
    cudaGetSymbolAddress((void**)&p_wil, g_wil);
    cudaGetSymbolAddress((void**)&p_woh, g_woh);
    cudaGetSymbolAddress((void**)&p_wol, g_wol);
    cudaGetSymbolAddress((void**)&p_f,   g_f);

    cudaFuncSetAttribute(gemm_mma_bf16x3,
                         cudaFuncAttributeMaxDynamicSharedMemorySize, GSMEM);

    // 1) LN + weight split + zero split-K region (one launch)
    prep_kernel<<<LN_BLKS + W_BLKS + Z_BLKS, 256>>>(q, k, v, gamma, beta, W_in, W_out);
    // 2) projection GEMM: 1184 full-K tiles + 96 tiles as 192 half-K CTAs
    gemm_mma_bf16x3<<<G1_GRID, 256, GSMEM>>>(
        p_ah, p_al, p_wih, p_wil, p_f, ROWS_TOT, DIMT, DIMT, nullptr, G1_FULL);
    // 3) per-(b,h) S partials
    kv_part_kernel<<<dim3(BB * NH, KVPARTS), 256>>>();
    // 4) attn = q_hat @ (reduced S) -> bf16 hi/lo
    qs_kernel<<<dim3(NQ / 64, BB * NH), 256>>>();
    // 5) output GEMM: 128x128 tiles, 256 CTAs, single wave
    gemm_mma_bf16x3<<<256, 256, GSMEM>>>(
        p_oh, p_ol, p_woh, p_wol, out, ROWS_Q, DIMT, DIMT, b_out, 256);
}

// round 17
// speedup vs baseline: 1.5528x; 1.0031x over previous
#include <cuda_runtime.h>
#include <cuda_bf16.h>
#include <cstdint>

// Problem constants
#define BB     4
#define NQ     1024
#define NK     2048
#define DIMT   1024
#define NH     16
#define DH     64
#define ROWS_Q (BB*NQ)                  // 4096
#define ROWS_K (BB*NK)                  // 8192
#define ROWS_TOT (ROWS_Q + 2*ROWS_K)    // 20480
#define KVPARTS 8

// GEMM1 tail-split constants: 1280 tiles total, 1184 full-K + 96 split-K(2)
#define G1_TILES     1280
#define G1_FULL      1184
#define G1_GRID      (G1_FULL + 2 * (G1_TILES - G1_FULL))   // 1376
#define SPLIT_ROW0   (148 * 128)                            // 18944

// prep grid layout: 2 LN rows per block
#define LN_BLKS      (ROWS_TOT / 2)                // 10240
#define W_BLKS       2048
#define Z_BLKS       (ROWS_TOT - SPLIT_ROW0)       // 1536

// Scratch (static device arrays: allocation-free per harness rules)
__device__ __nv_bfloat16 g_ah[(size_t)ROWS_TOT * DIMT];  // LN out, hi bf16
__device__ __nv_bfloat16 g_al[(size_t)ROWS_TOT * DIMT];  // LN out, lo bf16
__device__ float         g_f [(size_t)ROWS_TOT * DIMT];  // projected features (fp32)
__device__ float         g_Sp[KVPARTS*BB*NH*DH*DH];      // kv partial sums
__device__ __nv_bfloat16 g_oh[(size_t)ROWS_Q * DIMT];    // attn out, hi bf16
__device__ __nv_bfloat16 g_ol[(size_t)ROWS_Q * DIMT];    // attn out, lo bf16
__device__ __nv_bfloat16 g_wih[DIMT*DIMT], g_wil[DIMT*DIMT];  // W_in^T  hi/lo [N,K]
__device__ __nv_bfloat16 g_woh[DIMT*DIMT], g_wol[DIMT*DIMT];  // W_out^T hi/lo [N,K]

// ---------------------------------------------------------------------------
// Helpers
// ---------------------------------------------------------------------------
__device__ __forceinline__ uint32_t smem_u32(const void* p) {
    uint32_t a;
    asm("{ .reg .u64 t; cvta.to.shared.u64 t, %1; cvt.u32.u64 %0, t; }" : "=r"(a) : "l"(p));
    return a;
}
__device__ __forceinline__ void cp16(uint32_t saddr, const void* g) {
    asm volatile("cp.async.cg.shared.global [%0], [%1], 16;" :: "r"(saddr), "l"(g));
}
#define CP_COMMIT() asm volatile("cp.async.commit_group;" ::: "memory")
#define CP_WAIT(n)  asm volatile("cp.async.wait_group %0;" :: "n"(n) : "memory")

__device__ __forceinline__ void ldsm_x4(uint32_t* r, uint32_t addr) {
    asm volatile("ldmatrix.sync.aligned.m8n8.x4.shared.b16 {%0,%1,%2,%3}, [%4];"
                 : "=r"(r[0]), "=r"(r[1]), "=r"(r[2]), "=r"(r[3]) : "r"(addr));
}
__device__ __forceinline__ void mma16816(float* c, const uint32_t* a, const uint32_t* b) {
    asm volatile("mma.sync.aligned.m16n8k16.row.col.f32.bf16.bf16.f32 "
                 "{%0,%1,%2,%3}, {%4,%5,%6,%7}, {%8,%9}, {%0,%1,%2,%3};"
                 : "+f"(c[0]), "+f"(c[1]), "+f"(c[2]), "+f"(c[3])
                 : "r"(a[0]), "r"(a[1]), "r"(a[2]), "r"(a[3]), "r"(b[0]), "r"(b[1]));
}
__device__ __forceinline__ void split2(float x, __nv_bfloat16& h, __nv_bfloat16& l) {
    h = __float2bfloat16_rn(x);
    l = __float2bfloat16_rn(x - __bfloat162float(h));
}
__device__ __forceinline__ uint32_t packbf2(float a, float b) {
    return (uint32_t)__bfloat16_as_ushort(__float2bfloat16_rn(a)) |
           ((uint32_t)__bfloat16_as_ushort(__float2bfloat16_rn(b)) << 16);
}
// XOR chunk swizzle for 64B rows of 4x16B chunks: 16B-aligned, ldmatrix
// 8-row phases hit all 8 banks.
__device__ __forceinline__ uint32_t sw_off(uint32_t row, uint32_t chunk) {
    return row * 64u + (chunk ^ ((row >> 1) & 3u)) * 16u;
}
__device__ __forceinline__ const float* ln_src(
    int row, const float* q, const float* k, const float* v) {
    if (row < ROWS_Q)               return q + (size_t)row * DIMT;
    else if (row < ROWS_Q + ROWS_K) return k + (size_t)(row - ROWS_Q) * DIMT;
    else                            return v + (size_t)(row - ROWS_Q - ROWS_K) * DIMT;
}

// ---------------------------------------------------------------------------
// Kernel 1 (merged): LN (2 rows/block) | weight split | zero split region
// ---------------------------------------------------------------------------
__global__ void __launch_bounds__(256) prep_kernel(
    const float* __restrict__ q, const float* __restrict__ k,
    const float* __restrict__ v, const float* __restrict__ gamma,
    const float* __restrict__ beta,
    const float* __restrict__ W_in, const float* __restrict__ W_out)
{
    const int blk = blockIdx.x;
    const int t = threadIdx.x;

    if (blk >= LN_BLKS + W_BLKS) {
        int zrow = SPLIT_ROW0 + (blk - LN_BLKS - W_BLKS);
        reinterpret_cast<float4*>(g_f + (size_t)zrow * DIMT)[t] =
            make_float4(0.f, 0.f, 0.f, 0.f);
        return;
    }
    if (blk >= LN_BLKS) {
        __shared__ float ts[32][33];
        int wblk = blk - LN_BLKS;
        const float* W = (wblk < 1024) ? W_in : W_out;
        __nv_bfloat16* Th = (wblk < 1024) ? g_wih : g_woh;
        __nv_bfloat16* Tl = (wblk < 1024) ? g_wil : g_wol;
        wblk &= 1023;
        int n0 = (wblk & 31) * 32, k0 = (wblk >> 5) * 32;
        int tx = t & 31, ty = t >> 5;                    // 32 x 8
        #pragma unroll
        for (int j = 0; j < 4; j++)
            ts[ty + j * 8][tx] = W[(size_t)(k0 + ty + j * 8) * DIMT + n0 + tx];
        __syncthreads();
        #pragma unroll
        for (int j = 0; j < 4; j++) {
            int n = n0 + ty + j * 8, kk = k0 + tx;
            float x = ts[tx][ty + j * 8];
            __nv_bfloat16 h, l;
            split2(x, h, l);
            Th[(size_t)n * DIMT + kk] = h;
            Tl[(size_t)n * DIMT + kk] = l;
        }
        return;
    }

    const int row = blk * 2 + (t >> 7);
    const int u = t & 127;
    const float* src = ln_src(row, q, k, v);
    float4 x0 = reinterpret_cast<const float4*>(src)[2 * u];
    float4 x1 = reinterpret_cast<const float4*>(src)[2 * u + 1];

    float s  = (x0.x + x0.y + x0.z + x0.w) + (x1.x + x1.y + x1.z + x1.w);
    float ss = (x0.x*x0.x + x0.y*x0.y + x0.z*x0.z + x0.w*x0.w)
             + (x1.x*x1.x + x1.y*x1.y + x1.z*x1.z + x1.w*x1.w);
    #pragma unroll
    for (int o = 16; o > 0; o >>= 1) {
        s  += __shfl_xor_sync(0xffffffffu, s,  o);
        ss += __shfl_xor_sync(0xffffffffu, ss, o);
    }
    __shared__ float ws[2][4], wss[2][4];
    const int r = t >> 7, w_in = (t >> 5) & 3;
    if ((t & 31) == 0) { ws[r][w_in] = s; wss[r][w_in] = ss; }
    __syncthreads();
    float tot   = ws[r][0] + ws[r][1] + ws[r][2] + ws[r][3];
    float totss = wss[r][0] + wss[r][1] + wss[r][2] + wss[r][3];
    float mu  = tot * (1.0f / DIMT);
    float var = totss * (1.0f / DIMT) - mu * mu;       // biased, matches ref
    float rs  = rsqrtf(var + 1e-5f);

    float4 g0 = reinterpret_cast<const float4*>(gamma)[2 * u];
    float4 g1 = reinterpret_cast<const float4*>(gamma)[2 * u + 1];
    float4 b0 = reinterpret_cast<const float4*>(beta)[2 * u];
    float4 b1 = reinterpret_cast<const float4*>(beta)[2 * u + 1];

    float y[8];
    y[0] = (x0.x - mu) * rs * g0.x + b0.x;
    y[1] = (x0.y - mu) * rs * g0.y + b0.y;
    y[2] = (x0.z - mu) * rs * g0.z + b0.z;
    y[3] = (x0.w - mu) * rs * g0.w + b0.w;
    y[4] = (x1.x - mu) * rs * g1.x + b1.x;
    y[5] = (x1.y - mu) * rs * g1.y + b1.y;
    y[6] = (x1.z - mu) * rs * g1.z + b1.z;
    y[7] = (x1.w - mu) * rs * g1.w + b1.w;

    float hf[8], lf[8];
    #pragma unroll
    for (int i = 0; i < 8; i++) {
        __nv_bfloat16 h, l;
        split2(y[i], h, l);
        hf[i] = __bfloat162float(h);
        lf[i] = __bfloat162float(l);
    }
    uint4 uh = make_uint4(packbf2(hf[0], hf[1]), packbf2(hf[2], hf[3]),
                          packbf2(hf[4], hf[5]), packbf2(hf[6], hf[7]));
    uint4 ul = make_uint4(packbf2(lf[0], lf[1]), packbf2(lf[2], lf[3]),
                          packbf2(lf[4], lf[5]), packbf2(lf[6], lf[7]));
    reinterpret_cast<uint4*>(g_ah + (size_t)row * DIMT)[u] = uh;
    reinterpret_cast<uint4*>(g_al + (size_t)row * DIMT)[u] = ul;
}

// ---------------------------------------------------------------------------
// Kernel 2: mma.sync bf16x3 GEMM, flat grid with split-K tail wave.
// (protected R13/R16 shape)
// ---------------------------------------------------------------------------
#define BKG     32
#define ROWB    64                     // 64 B per row (32 bf16, unpadded)
#define TILE_B  (128 * ROWB)           // 8192 B per tensor tile
#define STAGE_B (4 * TILE_B)           // 32768 B per stage
#define GSMEM   (3 * STAGE_B)          // 98304 B total

__global__ void __launch_bounds__(256, 2) gemm_mma_bf16x3(
    const __nv_bfloat16* __restrict__ Ah, const __nv_bfloat16* __restrict__ Al,
    const __nv_bfloat16* __restrict__ Bh, const __nv_bfloat16* __restrict__ Bl,
    float* __restrict__ C, int M, int N, int K, const float* __restrict__ bias,
    int n_full)
{
    extern __shared__ char sm[];
    const uint32_t sbase = smem_u32(sm);
    const int tid = threadIdx.x;
    const int lane = tid & 31;
    const int wid = tid >> 5;
    const int warp_m = wid >> 2;        // 0..1
    const int warp_n = wid & 3;         // 0..3

    const int bid = blockIdx.x;
    int tile, k_begin, k_slabs;
    bool is_split;
    if (bid < n_full) {
        tile = bid; k_begin = 0; k_slabs = K / BKG; is_split = false;
    } else {
        int j = bid - n_full;
        tile = n_full + (j >> 1);
        k_begin = (j & 1) * (K / 2);
        k_slabs = K / (2 * BKG);
        is_split = true;
    }
    const int brow = tile >> 3, bcol = tile & 7;

    const __nv_bfloat16* tp[4] = {
        Ah + (size_t)brow * 128 * K + k_begin,
        Al + (size_t)brow * 128 * K + k_begin,
        Bh + (size_t)bcol * 128 * K + k_begin,
        Bl + (size_t)bcol * 128 * K + k_begin };

    int l_tens[8], l_row[8], l_ch[8];
    #pragma unroll
    for (int l = 0; l < 8; l++) {
        int id = l * 256 + tid;
        l_tens[l] = id >> 9;
        int u = id & 511;
        l_row[l] = u >> 2;
        l_ch[l] = u & 3;
    }

    float acc[4][4][4];
    #pragma unroll
    for (int i = 0; i < 4; i++)
        #pragma unroll
        for (int j = 0; j < 4; j++)
            #pragma unroll
            for (int c = 0; c < 4; c++) acc[i][j][c] = 0.f;

    #pragma unroll
    for (int pr = 0; pr < 2; pr++) {
        #pragma unroll
        for (int l = 0; l < 8; l++) {
            uint32_t sa = sbase + pr * STAGE_B + l_tens[l] * TILE_B
                        + sw_off((uint32_t)l_row[l], (uint32_t)l_ch[l]);
            cp16(sa, tp[l_tens[l]] + (size_t)l_row[l] * K + pr * BKG + l_ch[l] * 8);
        }
        CP_COMMIT();
    }

    const int b_rowlane = ((lane >> 4) & 1) * 8 + (lane & 7);
    const uint32_t b_kbit = (uint32_t)((lane >> 3) & 1);
    const uint32_t a_kbit = (uint32_t)(lane >> 4);
    const int bn = warp_n * 32;

    for (int ks = 0; ks < k_slabs; ks++) {
        if (ks + 2 < k_slabs) CP_WAIT(1); else CP_WAIT(0);
        __syncthreads();

        if (ks + 2 < k_slabs) {
            const int st = (ks + 2) % 3;
            const int k0 = (ks + 2) * BKG;
            #pragma unroll
            for (int l = 0; l < 8; l++) {
                uint32_t sa = sbase + st * STAGE_B + l_tens[l] * TILE_B
                            + sw_off((uint32_t)l_row[l], (uint32_t)l_ch[l]);
                cp16(sa, tp[l_tens[l]] + (size_t)l_row[l] * K + k0 + l_ch[l] * 8);
            }
            CP_COMMIT();
        }

        const uint32_t stb = sbase + (ks % 3) * STAGE_B;
        #pragma unroll
        for (int kk = 0; kk < 2; kk++) {
            const uint32_t bchunk = (uint32_t)(kk * 2) + b_kbit;
            const uint32_t achunk = (uint32_t)(kk * 2) + a_kbit;
            uint32_t bh[4][2], bl[4][2];
            #pragma unroll
            for (int p = 0; p < 2; p++) {
                uint32_t brr = (uint32_t)(bn + p * 16 + b_rowlane);
                uint32_t boff = sw_off(brr, bchunk);
                uint32_t r4[4];
                ldsm_x4(r4, stb + 2 * TILE_B + boff);
                bh[2*p][0] = r4[0]; bh[2*p][1] = r4[1];
                bh[2*p+1][0] = r4[2]; bh[2*p+1][1] = r4[3];
                ldsm_x4(r4, stb + 3 * TILE_B + boff);
                bl[2*p][0] = r4[0]; bl[2*p][1] = r4[1];
                bl[2*p+1][0] = r4[2]; bl[2*p+1][1] = r4[3];
            }
            #pragma unroll
            for (int mt = 0; mt < 4; mt++) {
                uint32_t ah4[4], al4[4];
                uint32_t arr = (uint32_t)(warp_m * 64 + mt * 16 + (lane & 15));
                uint32_t aoff = sw_off(arr, achunk);
                ldsm_x4(ah4, stb + aoff);
                ldsm_x4(al4, stb + TILE_B + aoff);
                #pragma unroll
                for (int nt = 0; nt < 4; nt++) mma16816(acc[mt][nt], ah4, bh[nt]);
                #pragma unroll
                for (int nt = 0; nt < 4; nt++) mma16816(acc[mt][nt], ah4, bl[nt]);
                #pragma unroll
                for (int nt = 0; nt < 4; nt++) mma16816(acc[mt][nt], al4, bh[nt]);
            }
        }
    }

    #pragma unroll
    for (int mt = 0; mt < 4; mt++) {
        const int row0 = brow * 128 + warp_m * 64 + mt * 16 + (lane >> 2);
        #pragma unroll
        for (int nt = 0; nt < 4; nt++) {
            const int col = bcol * 128 + warp_n * 32 + nt * 8 + (lane & 3) * 2;
            if (is_split) {
                atomicAdd(C + (size_t)row0 * N + col,           acc[mt][nt][0]);
                atomicAdd(C + (size_t)row0 * N + col + 1,       acc[mt][nt][1]);
                atomicAdd(C + (size_t)(row0 + 8) * N + col,     acc[mt][nt][2]);
                atomicAdd(C + (size_t)(row0 + 8) * N + col + 1, acc[mt][nt][3]);
            } else {
                float b0 = 0.f, b1 = 0.f;
                if (bias) { b0 = __ldg(&bias[col]); b1 = __ldg(&bias[col + 1]); }
                *reinterpret_cast<float2*>(C + (size_t)row0 * N + col) =
                    make_float2(acc[mt][nt][0] + b0, acc[mt][nt][1] + b1);
                *reinterpret_cast<float2*>(C + (size_t)(row0 + 8) * N + col) =
                    make_float2(acc[mt][nt][2] + b0, acc[mt][nt][3] + b1);
            }
        }
    }
}

// ---------------------------------------------------------------------------
// Kernel 3: kv partials, 64-row tiles (MLP=8 front-batched loads, 8 syncs
// per CTA instead of 128). grid = (64, KVPARTS) -> 512 CTAs (full-chip).
// ---------------------------------------------------------------------------
__global__ void __launch_bounds__(256) kv_part_kernel()
{
    const int bh = blockIdx.x;
    const int part = blockIdx.y;
    const int b = bh >> 4, h = bh & 15;
    __shared__ float sk[64][64];
    __shared__ float sv[64][64];
    __shared__ float rkn[64];
    const int t = threadIdx.x;
    const int j1_0 = (t >> 4) << 2;
    const int j2_0 = (t & 15) << 2;
    const int mbase = part * (NK / KVPARTS);
    const float* fk = g_f + (size_t)(ROWS_Q + b * NK + mbase) * DIMT + h * DH;
    const float* fv = g_f + (size_t)(ROWS_Q + ROWS_K + b * NK + mbase) * DIMT + h * DH;

    float acc[4][4];
    #pragma unroll
    for (int i = 0; i < 4; i++)
        #pragma unroll
        for (int j = 0; j < 4; j++) acc[i][j] = 0.f;

    for (int m0 = 0; m0 < NK / KVPARTS; m0 += 64) {
        // front-batch 8 independent float4 loads per thread (4 per tensor)
        float4 kv4[4], vv4[4];
        int rr[4], cc[4];
        #pragma unroll
        for (int l = 0; l < 4; l++) {
            int idx = t + l * 256;                 // 1024 float4s per tensor
            rr[l] = idx >> 4; cc[l] = (idx & 15) << 2;
            kv4[l] = *reinterpret_cast<const float4*>(&fk[(size_t)(m0 + rr[l]) * DIMT + cc[l]]);
            vv4[l] = *reinterpret_cast<const float4*>(&fv[(size_t)(m0 + rr[l]) * DIMT + cc[l]]);
        }
        #pragma unroll
        for (int l = 0; l < 4; l++) {
            *reinterpret_cast<float4*>(&sk[rr[l]][cc[l]]) = kv4[l];
            *reinterpret_cast<float4*>(&sv[rr[l]][cc[l]]) = vv4[l];
            float s = kv4[l].x*kv4[l].x + kv4[l].y*kv4[l].y
                    + kv4[l].z*kv4[l].z + kv4[l].w*kv4[l].w;
            #pragma unroll
            for (int o = 8; o > 0; o >>= 1) s += __shfl_xor_sync(0xffffffffu, s, o);
            if ((t & 15) == 0) rkn[rr[l]] = rsqrtf(s);
        }
        __syncthreads();
        #pragma unroll 8
        for (int m = 0; m < 64; m++) {
            float rk = rkn[m];
            float4 a  = *reinterpret_cast<float4*>(&sk[m][j1_0]);
            float4 bq = *reinterpret_cast<float4*>(&sv[m][j2_0]);
            float a0 = a.x * rk, a1 = a.y * rk, a2 = a.z * rk, a3 = a.w * rk;
            acc[0][0] = fmaf(a0, bq.x, acc[0][0]); acc[0][1] = fmaf(a0, bq.y, acc[0][1]);
            acc[0][2] = fmaf(a0, bq.z, acc[0][2]); acc[0][3] = fmaf(a0, bq.w, acc[0][3]);
            acc[1][0] = fmaf(a1, bq.x, acc[1][0]); acc[1][1] = fmaf(a1, bq.y, acc[1][1]);
            acc[1][2] = fmaf(a1, bq.z, acc[1][2]); acc[1][3] = fmaf(a1, bq.w, acc[1][3]);
            acc[2][0] = fmaf(a2, bq.x, acc[2][0]); acc[2][1] = fmaf(a2, bq.y, acc[2][1]);
            acc[2][2] = fmaf(a2, bq.z, acc[2][2]); acc[2][3] = fmaf(a2, bq.w, acc[2][3]);
            acc[3][0] = fmaf(a3, bq.x, acc[3][0]); acc[3][1] = fmaf(a3, bq.y, acc[3][1]);
            acc[3][2] = fmaf(a3, bq.z, acc[3][2]); acc[3][3] = fmaf(a3, bq.w, acc[3][3]);
        }
        __syncthreads();
    }
    float* Sp = g_Sp + ((size_t)part * (BB * NH) + bh) * (DH * DH);
    #pragma unroll
    for (int i = 0; i < 4; i++)
        *reinterpret_cast<float4*>(&Sp[(j1_0 + i) * DH + j2_0]) =
            make_float4(acc[i][0], acc[i][1], acc[i][2], acc[i][3]);
}

// ---------------------------------------------------------------------------
// Kernel 4: out_attn = (f_q/|f_q|) @ S[b,h]  -> bf16 hi/lo split.
// 64 q-rows per CTA (protected shape); S reduced in-kernel from 8 partials.
// ---------------------------------------------------------------------------
__global__ void __launch_bounds__(256) qs_kernel()
{
    const int bh = blockIdx.y;
    const int nt = blockIdx.x;
    const int b = bh >> 4, h = bh & 15;
    __shared__ float sS[64][64];
    __shared__ float sq[64][68];          // row-major, norm folded
    const int t = threadIdx.x;

    // reduce 8 partials into sS (each thread owns 4 float4 slots)
    {
        float4 racc[4];
        const float4* P0 = reinterpret_cast<const float4*>(
            g_Sp + ((size_t)0 * (BB * NH) + bh) * (DH * DH));
        #pragma unroll
        for (int l = 0; l < 4; l++) racc[l] = P0[t + l * 256];
        #pragma unroll
        for (int p = 1; p < KVPARTS; p++) {
            const float4* Pp = reinterpret_cast<const float4*>(
                g_Sp + ((size_t)p * (BB * NH) + bh) * (DH * DH));
            #pragma unroll
            for (int l = 0; l < 4; l++) {
                float4 v = Pp[t + l * 256];
                racc[l].x += v.x; racc[l].y += v.y;
                racc[l].z += v.z; racc[l].w += v.w;
            }
        }
        #pragma unroll
        for (int l = 0; l < 4; l++)
            reinterpret_cast<float4*>(sS)[t + l * 256] = racc[l];
    }

    const float* fq = g_f + (size_t)(b * NQ + nt * 64) * DIMT + h * DH;
    #pragma unroll
    for (int l = 0; l < 4; l++) {
        int idx = t + l * 256;
        int r = idx >> 4, c = (idx & 15) << 2;
        float4 x = *reinterpret_cast<const float4*>(&fq[(size_t)r * DIMT + c]);
        float s = x.x*x.x + x.y*x.y + x.z*x.z + x.w*x.w;
        #pragma unroll
        for (int o = 8; o > 0; o >>= 1) s += __shfl_xor_sync(0xffffffffu, s, o);
        float rq = rsqrtf(s);
        *reinterpret_cast<float4*>(&sq[r][c]) =
            make_float4(x.x * rq, x.y * rq, x.z * rq, x.w * rq);
    }
    __syncthreads();

    float acc[4][4];
    #pragma unroll
    for (int i = 0; i < 4; i++)
        #pragma unroll
        for (int j = 0; j < 4; j++) acc[i][j] = 0.f;
    const int r0 = (t >> 4) << 2, c0 = (t & 15) << 2;
    #pragma unroll 8
    for (int j1 = 0; j1 < 64; j1++) {
        float a0 = sq[r0 + 0][j1];
        float a1 = sq[r0 + 1][j1];
        float a2 = sq[r0 + 2][j1];
        float a3 = sq[r0 + 3][j1];
        float4 bq = *reinterpret_cast<float4*>(&sS[j1][c0]);
        acc[0][0] = fmaf(a0, bq.x, acc[0][0]); acc[0][1] = fmaf(a0, bq.y, acc[0][1]);
        acc[0][2] = fmaf(a0, bq.z, acc[0][2]); acc[0][3] = fmaf(a0, bq.w, acc[0][3]);
        acc[1][0] = fmaf(a1, bq.x, acc[1][0]); acc[1][1] = fmaf(a1, bq.y, acc[1][1]);
        acc[1][2] = fmaf(a1, bq.z, acc[1][2]); acc[1][3] = fmaf(a1, bq.w, acc[1][3]);
        acc[2][0] = fmaf(a2, bq.x, acc[2][0]); acc[2][1] = fmaf(a2, bq.y, acc[2][1]);
        acc[2][2] = fmaf(a2, bq.z, acc[2][2]); acc[2][3] = fmaf(a2, bq.w, acc[2][3]);
        acc[3][0] = fmaf(a3, bq.x, acc[3][0]); acc[3][1] = fmaf(a3, bq.y, acc[3][1]);
        acc[3][2] = fmaf(a3, bq.z, acc[3][2]); acc[3][3] = fmaf(a3, bq.w, acc[3][3]);
    }
    const size_t obase = (size_t)(b * NQ + nt * 64 + r0) * DIMT + h * DH + c0;
    #pragma unroll
    for (int i = 0; i < 4; i++) {
        __nv_bfloat16 h0, h1, h2, h3, l0, l1, l2, l3;
        split2(acc[i][0], h0, l0); split2(acc[i][1], h1, l1);
        split2(acc[i][2], h2, l2); split2(acc[i][3], h3, l3);
        ushort4 uh = make_ushort4(__bfloat16_as_ushort(h0), __bfloat16_as_ushort(h1),
                                  __bfloat16_as_ushort(h2), __bfloat16_as_ushort(h3));
        ushort4 ul = make_ushort4(__bfloat16_as_ushort(l0), __bfloat16_as_ushort(l1),
                                  __bfloat16_as_ushort(l2), __bfloat16_as_ushort(l3));
        *reinterpret_cast<ushort4*>(g_oh + obase + (size_t)i * DIMT) = uh;
        *reinterpret_cast<ushort4*>(g_ol + obase + (size_t)i * DIMT) = ul;
    }
}

// ---------------------------------------------------------------------------
extern "C" void kernel_launch(void* const* d_in, const int* in_sizes, int n_in,
                              void* d_out, int out_size)
{
    const float* q     = (const float*)d_in[0];
    const float* k     = (const float*)d_in[1];
    const float* v     = (const float*)d_in[2];
    const float* gamma = (const float*)d_in[3];
    const float* beta  = (const float*)d_in[4];
    const float* W_in  = (const float*)d_in[5];
    const float* W_out = (const float*)d_in[6];
    const float* b_out = (const float*)d_in[7];
    float* out = (float*)d_out;

    __nv_bfloat16 *p_ah, *p_al, *p_oh, *p_ol, *p_wih, *p_wil, *p_woh, *p_wol;
    float *p_f;
    cudaGetSymbolAddress((void**)&p_ah,  g_ah);
    cudaGetSymbolAddress((void**)&p_al,  g_al);
    cudaGetSymbolAddress((void**)&p_oh,  g_oh);
    cudaGetSymbolAddress((void**)&p_ol,  g_ol);
    cudaGetSymbolAddress((void**)&p_wih, g_wih);
    cudaGetSymbolAddress((void**)&p_wil, g_wil);
    cudaGetSymbolAddress((void**)&p_woh, g_woh);
    cudaGetSymbolAddress((void**)&p_wol, g_wol);
    cudaGetSymbolAddress((void**)&p_f,   g_f);

    cudaFuncSetAttribute(gemm_mma_bf16x3,
                         cudaFuncAttributeMaxDynamicSharedMemorySize, GSMEM);

    // 1) LN + weight split + zero split-K region (one launch)
    prep_kernel<<<LN_BLKS + W_BLKS + Z_BLKS, 256>>>(q, k, v, gamma, beta, W_in, W_out);
    // 2) projection GEMM: 1184 full-K tiles + 96 tiles as 192 half-K CTAs
    gemm_mma_bf16x3<<<G1_GRID, 256, GSMEM>>>(
        p_ah, p_al, p_wih, p_wil, p_f, ROWS_TOT, DIMT, DIMT, nullptr, G1_FULL);
    // 3) per-(b,h) S partials
    kv_part_kernel<<<dim3(BB * NH, KVPARTS), 256>>>();
    // 4) attn = q_hat @ (reduced S) -> bf16 hi/lo
    qs_kernel<<<dim3(NQ / 64, BB * NH), 256>>>();
    // 5) output GEMM: 128x128 tiles, 256 CTAs, single wave
    gemm_mma_bf16x3<<<256, 256, GSMEM>>>(
        p_oh, p_ol, p_woh, p_wol, out, ROWS_Q, DIMT, DIMT, b_out, 256);
}